// round 3
// baseline (speedup 1.0000x reference)
#include <cuda_runtime.h>

#define NN 8192
#define EE 131072
#define ND 128
#define HD 256
#define NWORDS (NN / 32)            // 256 words per adjacency row
#define ADJ_WORDS (NN * NWORDS)     // 2M words = 8 MiB
#define MAXROW 128                  // per-row distinct-neighbor cap (~45 actual max)

// Scratch (no allocations allowed — device globals per harness rules)
__device__ unsigned g_adj[ADJ_WORDS];
__device__ int      g_deg[NN];
__device__ int      g_nbr[NN * MAXROW];    // 4 MB compact adjacency
__device__ float    g_dinv[NN];
__device__ float    g_xs[NN * ND];
__device__ float    g_mid[NN * ND];
__device__ int      g_is64;

// ---------------------------------------------------------------------------
// Clear bitmap (uint4) + init degrees + parallel int64/int32 detection.
// Values are in [0,8192): an int64 little-endian buffer has every odd 32-bit
// word == 0; an int32 buffer has random indices there. 64 parallel probes.
// ---------------------------------------------------------------------------
__global__ void k_clear(const unsigned* __restrict__ ei) {
    int i = blockIdx.x * blockDim.x + threadIdx.x;
    if (i < ADJ_WORDS / 4) ((uint4*)g_adj)[i] = make_uint4(0u, 0u, 0u, 0u);
    if (i < NN) g_deg[i] = 1;                       // the +I term

    if (blockIdx.x == 0) {
        __shared__ int s_ok;
        if (threadIdx.x == 0) s_ok = 1;
        __syncthreads();
        if (threadIdx.x < 64 && ei[2 * threadIdx.x + 1] != 0u) s_ok = 0;
        __syncthreads();
        if (threadIdx.x == 0) g_is64 = s_ok;
    }
}

// Scatter edges: bitmap gives exact dedup; first-setter appends to the
// compact per-row neighbor list and bumps the degree.
__global__ void k_scatter(const void* __restrict__ ei) {
    int e = blockIdx.x * blockDim.x + threadIdx.x;
    if (e >= EE) return;
    int s, t;
    if (g_is64) {
        const long long* p = (const long long*)ei;
        s = (int)p[e];
        t = (int)p[EE + e];
    } else {
        const int* p = (const int*)ei;
        s = p[e];
        t = p[EE + e];
    }
    unsigned idx  = (unsigned)s * NN + (unsigned)t;
    unsigned mask = 1u << (idx & 31u);
    unsigned old  = atomicOr(&g_adj[idx >> 5], mask);
    if (!(old & mask)) {
        int slot = atomicAdd(&g_deg[s], 1) - 1;     // deg starts at 1
        if (slot < MAXROW) g_nbr[s * MAXROW + slot] = t;
    }
}

// xs[i,:] = d_i^{-1/2} * x[i,:]   (float4)
__global__ void k_scale(const float* __restrict__ x) {
    int gid = blockIdx.x * blockDim.x + threadIdx.x;   // NN*ND/4 threads
    int i = gid >> 5;                                   // 32 float4 per row
    float dinv = rsqrtf((float)g_deg[i]);
    if ((gid & 31) == 0) g_dinv[i] = dinv;
    float4 v = ((const float4*)x)[gid];
    v.x *= dinv; v.y *= dinv; v.z *= dinv; v.w *= dinv;
    ((float4*)g_xs)[gid] = v;
}

// mid[i,:] = d_i^{-1/2} * ( xs[i,:] + sum_{j in nbr(i)} xs[j,:] )
// One WARP per row; lane = one float4 of the 128 features. No scan, no smem.
__global__ void __launch_bounds__(256) k_aggregate() {
    int warp = threadIdx.x >> 5;
    int lane = threadIdx.x & 31;
    int i = blockIdx.x * 8 + warp;

    const float4* xs4 = (const float4*)g_xs;
    float4 acc = xs4[i * 32 + lane];                 // the +I self term
    int n = min(g_deg[i] - 1, MAXROW);
    const int* __restrict__ lst = g_nbr + (size_t)i * MAXROW;

    int k = 0;
    for (; k + 3 < n; k += 4) {                      // 4 independent gathers (MLP)
        int j0 = __ldg(lst + k + 0);
        int j1 = __ldg(lst + k + 1);
        int j2 = __ldg(lst + k + 2);
        int j3 = __ldg(lst + k + 3);
        float4 a0 = xs4[j0 * 32 + lane];
        float4 a1 = xs4[j1 * 32 + lane];
        float4 a2 = xs4[j2 * 32 + lane];
        float4 a3 = xs4[j3 * 32 + lane];
        acc.x += (a0.x + a1.x) + (a2.x + a3.x);
        acc.y += (a0.y + a1.y) + (a2.y + a3.y);
        acc.z += (a0.z + a1.z) + (a2.z + a3.z);
        acc.w += (a0.w + a1.w) + (a2.w + a3.w);
    }
    for (; k < n; k++) {
        int j = __ldg(lst + k);
        float4 a = xs4[j * 32 + lane];
        acc.x += a.x; acc.y += a.y; acc.z += a.z; acc.w += a.w;
    }

    float dinv = g_dinv[i];
    acc.x *= dinv; acc.y *= dinv; acc.z *= dinv; acc.w *= dinv;
    ((float4*)g_mid)[i * 32 + lane] = acc;
}

// out[i,h] = sum_k mid[i,k] * W[h,k]   (W is [256,128] row-major)
// 16 rows per block, 256 threads (thread = output column h).
// Inner product via packed fma.rn.f32x2 (2 fp32 FMAs / instr, full precision).
#define GI 16
__global__ void __launch_bounds__(256) k_gemm(const float* __restrict__ W,
                                              float* __restrict__ out) {
    __shared__ __align__(16) float sm[GI * ND];
    int h  = threadIdx.x;
    int i0 = blockIdx.x * GI;

    for (int idx = h; idx < GI * ND; idx += 256) sm[idx] = g_mid[i0 * ND + idx];
    __syncthreads();

    unsigned long long acc2[GI];                     // packed (even_k, odd_k) partials
    #pragma unroll
    for (int ii = 0; ii < GI; ii++) acc2[ii] = 0ull; // = (0.0f, 0.0f)

    const float4* W4 = (const float4*)(W + h * ND);  // 512B-aligned per thread
    #pragma unroll 4
    for (int kq = 0; kq < ND / 4; kq++) {
        union { float4 f; unsigned long long u[2]; } w;
        w.f = W4[kq];
        #pragma unroll
        for (int ii = 0; ii < GI; ii++) {
            union { float4 f; unsigned long long u[2]; } s;
            s.f = *(const float4*)&sm[ii * ND + kq * 4];   // warp-broadcast LDS.128
            asm("fma.rn.f32x2 %0, %1, %2, %0;" : "+l"(acc2[ii]) : "l"(s.u[0]), "l"(w.u[0]));
            asm("fma.rn.f32x2 %0, %1, %2, %0;" : "+l"(acc2[ii]) : "l"(s.u[1]), "l"(w.u[1]));
        }
    }
    #pragma unroll
    for (int ii = 0; ii < GI; ii++) {
        float lo = __uint_as_float((unsigned)(acc2[ii] & 0xffffffffull));
        float hi = __uint_as_float((unsigned)(acc2[ii] >> 32));
        out[(size_t)(i0 + ii) * HD + h] = lo + hi;
    }
}

extern "C" void kernel_launch(void* const* d_in, const int* in_sizes, int n_in,
                              void* d_out, int out_size) {
    const float* x  = (const float*)d_in[0];
    const void*  ei = d_in[1];
    const float* W  = (const float*)d_in[2];
    float*       out = (float*)d_out;

    k_clear<<<(ADJ_WORDS / 4 + 255) / 256, 256>>>((const unsigned*)ei);
    k_scatter<<<(EE + 255) / 256, 256>>>(ei);
    k_scale<<<(NN * ND / 4) / 256, 256>>>(x);
    k_aggregate<<<NN / 8, 256>>>();
    k_gemm<<<NN / GI, 256>>>(W, out);
}